// round 1
// baseline (speedup 1.0000x reference)
#include <cuda_runtime.h>
#include <math.h>

#define NN 100000
#define NE 1200000
#define NC 64
#define NG 256
#define EPSBN 1e-5f

// ---------------- static scratch (no allocation allowed) ----------------
__device__ float  d_h[NN * NC];        // node features
__device__ float  d_y[NN * NC];        // pre-BN buffer / aggregation target
__device__ float  d_A[NN * 2 * NC];    // [Af | As] per node (dst-side projections)
__device__ float  d_B[NN * 2 * NC];    // [Bf | Bs] per node (src-side projections)
__device__ int    d_cnt[NN];
__device__ int    d_fill[NN];
__device__ int    d_off[NN + 1];
__device__ int    d_srcs[NE];          // src ids sorted by dst
__device__ float  d_eas[NE];           // edge attrs sorted by dst
__device__ double d_stats[2 * NC];     // BN sum / sumsq
__device__ float  d_bnscale[NC];
__device__ float  d_bnshift[NC];
__device__ float  d_pool[NG * NC];
__device__ int    d_gcnt[NG];

// ---------------- CSR build ----------------
__global__ void zero_counts_kernel() {
    int i = blockIdx.x * blockDim.x + threadIdx.x;
    if (i < NN) { d_cnt[i] = 0; d_fill[i] = 0; }
}

__global__ void hist_kernel(const int* __restrict__ ei) {
    int e = blockIdx.x * blockDim.x + threadIdx.x;
    if (e < NE) atomicAdd(&d_cnt[ei[NE + e]], 1);
}

__global__ void scan_kernel() {
    // 1024 threads, chunked exclusive scan over d_cnt -> d_off
    const int CH = (NN + 1023) / 1024;   // 98
    int tid = threadIdx.x;
    int start = tid * CH;
    int end = min(start + CH, NN);
    int s = 0;
    for (int i = start; i < end; i++) s += d_cnt[i];

    __shared__ int warp_sums[32];
    int lane = tid & 31, w = tid >> 5;
    int incl = s;
    #pragma unroll
    for (int o = 1; o < 32; o <<= 1) {
        int t = __shfl_up_sync(0xffffffffu, incl, o);
        if (lane >= o) incl += t;
    }
    if (lane == 31) warp_sums[w] = incl;
    __syncthreads();
    if (w == 0) {
        int v = warp_sums[lane];
        #pragma unroll
        for (int o = 1; o < 32; o <<= 1) {
            int t = __shfl_up_sync(0xffffffffu, v, o);
            if (lane >= o) v += t;
        }
        warp_sums[lane] = v;
    }
    __syncthreads();
    int excl = incl - s + (w > 0 ? warp_sums[w - 1] : 0);
    int run = excl;
    for (int i = start; i < end; i++) { d_off[i] = run; run += d_cnt[i]; }
    if (tid == 1023) d_off[NN] = NE;
}

__global__ void scatter_kernel(const int* __restrict__ ei, const float* __restrict__ ea) {
    int e = blockIdx.x * blockDim.x + threadIdx.x;
    if (e < NE) {
        int d = ei[NE + e];
        int p = atomicAdd(&d_fill[d], 1);
        int idx = d_off[d] + p;
        d_srcs[idx] = ei[e];
        d_eas[idx] = ea[e];
    }
}

// ---------------- BN helpers ----------------
__global__ void zero_stats_kernel() {
    int i = threadIdx.x;
    if (i < 2 * NC) d_stats[i] = 0.0;
}

__global__ void bn_prep_kernel(const float* __restrict__ g, const float* __restrict__ beta) {
    int c = threadIdx.x;
    if (c < NC) {
        double mu = d_stats[c] / (double)NN;
        double var = d_stats[NC + c] / (double)NN - mu * mu;
        float rs = rsqrtf((float)var + EPSBN);
        float sc = g[c] * rs;
        d_bnscale[c] = sc;
        d_bnshift[c] = beta[c] - (float)mu * sc;
    }
}

__global__ void bn_apply_kernel(int residual, int relu) {
    int idx = blockIdx.x * blockDim.x + threadIdx.x;
    if (idx >= NN * NC) return;
    int c = idx & 63;
    float v = fmaf(d_y[idx], d_bnscale[c], d_bnshift[c]);
    if (residual) v += d_h[idx];
    if (relu) v = fmaxf(v, 0.f);
    d_h[idx] = v;
}

// ---------------- input layer: y = x @ W_in + b_in (12 -> 64) + BN stats ----------------
__global__ __launch_bounds__(256) void input_kernel(const float* __restrict__ x,
                                                    const float* __restrict__ W,
                                                    const float* __restrict__ b) {
    __shared__ float ws[12 * 64];
    __shared__ float xs[4 * 12];
    __shared__ float ssum[64], ssq[64];
    int tid = threadIdx.x;
    int base = blockIdx.x * 4;
    for (int i = tid; i < 12 * 64; i += 256) ws[i] = W[i];
    if (tid < 48) {
        int n = tid / 12, k = tid % 12;
        xs[tid] = (base + n < NN) ? x[(base + n) * 12 + k] : 0.f;
    }
    if (tid < 64) { ssum[tid] = 0.f; ssq[tid] = 0.f; }
    __syncthreads();
    int n = tid >> 6;
    int c = tid & 63;
    float acc = b[c];
    #pragma unroll
    for (int k = 0; k < 12; k++) acc = fmaf(xs[n * 12 + k], ws[k * 64 + c], acc);
    if (base + n < NN) {
        d_y[(size_t)(base + n) * 64 + c] = acc;
        atomicAdd(&ssum[c], acc);
        atomicAdd(&ssq[c], acc * acc);
    }
    __syncthreads();
    if (tid < 64) {
        atomicAdd(&d_stats[tid], (double)ssum[tid]);
        atomicAdd(&d_stats[64 + tid], (double)ssq[tid]);
    }
}

// ---------------- per-node projections: A = h@W[0:64], B = h@W[64:128] for f and s ----------------
__global__ __launch_bounds__(256) void gemm_AB_kernel(const float* __restrict__ Wf,
                                                      const float* __restrict__ Ws) {
    // blockIdx.y = quadrant: 0: A/f, 1: A/s, 2: B/f, 3: B/s
    __shared__ __align__(16) float hsT[64][64];  // [k][node]
    __shared__ __align__(16) float wsm[64][64];  // [k][c]
    int tid = threadIdx.x;
    int q = blockIdx.y;
    const float* Wbase = ((q == 0 || q == 2) ? Wf : Ws) + ((q >= 2) ? 64 * 64 : 0);
    int nb = blockIdx.x * 64;

    #pragma unroll
    for (int m = 0; m < 16; m++) {
        int lin = m * 256 + tid;
        int a = lin >> 6, bidx = lin & 63;
        float v = (nb + a < NN) ? d_h[(size_t)(nb + a) * 64 + bidx] : 0.f;
        hsT[bidx][a] = v;
        wsm[a][bidx] = Wbase[lin];
    }
    __syncthreads();

    int tx = tid & 15, ty = tid >> 4;
    float acc[4][4] = {};
    #pragma unroll
    for (int k = 0; k < 64; k++) {
        float4 av = *(const float4*)&hsT[k][ty * 4];
        float4 bv = *(const float4*)&wsm[k][tx * 4];
        acc[0][0] = fmaf(av.x, bv.x, acc[0][0]); acc[0][1] = fmaf(av.x, bv.y, acc[0][1]);
        acc[0][2] = fmaf(av.x, bv.z, acc[0][2]); acc[0][3] = fmaf(av.x, bv.w, acc[0][3]);
        acc[1][0] = fmaf(av.y, bv.x, acc[1][0]); acc[1][1] = fmaf(av.y, bv.y, acc[1][1]);
        acc[1][2] = fmaf(av.y, bv.z, acc[1][2]); acc[1][3] = fmaf(av.y, bv.w, acc[1][3]);
        acc[2][0] = fmaf(av.z, bv.x, acc[2][0]); acc[2][1] = fmaf(av.z, bv.y, acc[2][1]);
        acc[2][2] = fmaf(av.z, bv.z, acc[2][2]); acc[2][3] = fmaf(av.z, bv.w, acc[2][3]);
        acc[3][0] = fmaf(av.w, bv.x, acc[3][0]); acc[3][1] = fmaf(av.w, bv.y, acc[3][1]);
        acc[3][2] = fmaf(av.w, bv.z, acc[3][2]); acc[3][3] = fmaf(av.w, bv.w, acc[3][3]);
    }
    float* outp = (q < 2) ? d_A : d_B;
    int coff = (q & 1) ? 64 : 0;
    #pragma unroll
    for (int r = 0; r < 4; r++) {
        int n = nb + ty * 4 + r;
        if (n < NN) {
            float4 v = make_float4(acc[r][0], acc[r][1], acc[r][2], acc[r][3]);
            *(float4*)&outp[(size_t)n * 128 + coff + tx * 4] = v;
        }
    }
}

// ---------------- edge pass: warp per dst node, gather B[src], gate, accumulate ----------------
__global__ __launch_bounds__(256) void edge_agg_kernel(const float* __restrict__ Wf,
                                                       const float* __restrict__ bf,
                                                       const float* __restrict__ Ws,
                                                       const float* __restrict__ bs) {
    __shared__ float ssum[64], ssq[64];
    int tid = threadIdx.x;
    if (tid < 64) { ssum[tid] = 0.f; ssq[tid] = 0.f; }
    __syncthreads();

    int lane = tid & 31, w = tid >> 5;
    int node = blockIdx.x * 8 + w;
    if (node < NN) {
        int c0 = lane, c1 = lane + 32;
        const float* Ap = d_A + (size_t)node * 128;
        float af0 = Ap[c0], af1 = Ap[c1], as0 = Ap[64 + c0], as1 = Ap[64 + c1];
        float wf0 = Wf[128 * 64 + c0], wf1 = Wf[128 * 64 + c1];
        float ws0 = Ws[128 * 64 + c0], ws1 = Ws[128 * 64 + c1];
        float bf0 = bf[c0], bf1 = bf[c1], bs0 = bs[c0], bs1 = bs[c1];
        float acc0 = 0.f, acc1 = 0.f;
        int e0 = d_off[node], e1 = d_off[node + 1];
        for (int e = e0; e < e1; e++) {
            int s = d_srcs[e];
            float ea = d_eas[e];
            const float* Bp = d_B + (size_t)s * 128;
            float tf0 = af0 + Bp[c0]      + fmaf(ea, wf0, bf0);
            float tf1 = af1 + Bp[c1]      + fmaf(ea, wf1, bf1);
            float ts0 = as0 + Bp[64 + c0] + fmaf(ea, ws0, bs0);
            float ts1 = as1 + Bp[64 + c1] + fmaf(ea, ws1, bs1);
            float sg0 = __fdividef(1.f, 1.f + __expf(-tf0));
            float sg1 = __fdividef(1.f, 1.f + __expf(-tf1));
            float sp0 = fmaxf(ts0, 0.f) + __logf(1.f + __expf(-fabsf(ts0)));
            float sp1 = fmaxf(ts1, 0.f) + __logf(1.f + __expf(-fabsf(ts1)));
            acc0 = fmaf(sg0, sp0, acc0);
            acc1 = fmaf(sg1, sp1, acc1);
        }
        d_y[(size_t)node * 64 + c0] = acc0;
        d_y[(size_t)node * 64 + c1] = acc1;
        atomicAdd(&ssum[c0], acc0); atomicAdd(&ssq[c0], acc0 * acc0);
        atomicAdd(&ssum[c1], acc1); atomicAdd(&ssq[c1], acc1 * acc1);
    }
    __syncthreads();
    if (tid < 64) {
        atomicAdd(&d_stats[tid], (double)ssum[tid]);
        atomicAdd(&d_stats[64 + tid], (double)ssq[tid]);
    }
}

// ---------------- pooling + final MLP ----------------
__global__ void zero_pool_kernel() {
    int i = blockIdx.x * blockDim.x + threadIdx.x;
    if (i < NG * NC) d_pool[i] = 0.f;
    if (i < NG) d_gcnt[i] = 0;
}

__global__ void pool_kernel(const int* __restrict__ batch) {
    int idx = blockIdx.x * blockDim.x + threadIdx.x;
    if (idx >= NN * NC) return;
    int i = idx >> 6, c = idx & 63;
    int g = batch[i];
    atomicAdd(&d_pool[g * 64 + c], d_h[idx]);
    if (c == 0) atomicAdd(&d_gcnt[g], 1);
}

__global__ void mlp_kernel(const float* __restrict__ W1, const float* __restrict__ b1,
                           const float* __restrict__ W2, const float* __restrict__ b2,
                           float* __restrict__ out) {
    __shared__ float p[64];
    __shared__ float h1[32];
    int g = blockIdx.x;
    int tid = threadIdx.x;
    float inv = 1.f / fmaxf((float)d_gcnt[g], 1.f);
    p[tid] = d_pool[g * 64 + tid] * inv;
    __syncthreads();
    if (tid < 32) {
        float a = b1[tid];
        #pragma unroll
        for (int k = 0; k < 64; k++) a = fmaf(p[k], W1[k * 32 + tid], a);
        h1[tid] = fmaxf(a, 0.f);
    }
    __syncthreads();
    if (tid < 32) {
        float v = h1[tid] * W2[tid];
        #pragma unroll
        for (int o = 16; o > 0; o >>= 1) v += __shfl_down_sync(0xffffffffu, v, o);
        if (tid == 0) out[g] = v + b2[0];
    }
}

// ---------------- launcher ----------------
extern "C" void kernel_launch(void* const* d_in, const int* in_sizes, int n_in,
                              void* d_out, int out_size) {
    const float* x     = (const float*)d_in[0];
    const int*   ei    = (const int*)d_in[1];
    const float* ea    = (const float*)d_in[2];
    const int*   batch = (const int*)d_in[3];
    const float* W_in  = (const float*)d_in[4];
    const float* b_in  = (const float*)d_in[5];
    const float* g0    = (const float*)d_in[6];
    const float* beta0 = (const float*)d_in[7];
    const float* Wf[3] = {(const float*)d_in[8],  (const float*)d_in[14], (const float*)d_in[20]};
    const float* bf[3] = {(const float*)d_in[9],  (const float*)d_in[15], (const float*)d_in[21]};
    const float* Ws[3] = {(const float*)d_in[10], (const float*)d_in[16], (const float*)d_in[22]};
    const float* bs[3] = {(const float*)d_in[11], (const float*)d_in[17], (const float*)d_in[23]};
    const float* gg[3] = {(const float*)d_in[12], (const float*)d_in[18], (const float*)d_in[24]};
    const float* bb[3] = {(const float*)d_in[13], (const float*)d_in[19], (const float*)d_in[25]};
    const float* W1 = (const float*)d_in[26];
    const float* b1 = (const float*)d_in[27];
    const float* W2 = (const float*)d_in[28];
    const float* b2 = (const float*)d_in[29];
    float* out = (float*)d_out;

    // CSR build (edges are the same for all 3 layers)
    zero_counts_kernel<<<(NN + 255) / 256, 256>>>();
    hist_kernel<<<(NE + 255) / 256, 256>>>(ei);
    scan_kernel<<<1, 1024>>>();
    scatter_kernel<<<(NE + 255) / 256, 256>>>(ei, ea);

    // input layer: h = relu(BN(x @ W_in + b_in))
    zero_stats_kernel<<<1, 128>>>();
    input_kernel<<<(NN + 3) / 4, 256>>>(x, W_in, b_in);
    bn_prep_kernel<<<1, 64>>>(g0, beta0);
    bn_apply_kernel<<<(NN * NC + 255) / 256, 256>>>(0, 1);

    // 3 CGConv layers
    for (int l = 0; l < 3; l++) {
        gemm_AB_kernel<<<dim3((NN + 63) / 64, 4), 256>>>(Wf[l], Ws[l]);
        zero_stats_kernel<<<1, 128>>>();
        edge_agg_kernel<<<(NN + 7) / 8, 256>>>(Wf[l], bf[l], Ws[l], bs[l]);
        bn_prep_kernel<<<1, 64>>>(gg[l], bb[l]);
        bn_apply_kernel<<<(NN * NC + 255) / 256, 256>>>(1, (l < 2) ? 1 : 0);
    }

    // pooling + MLP head
    zero_pool_kernel<<<(NG * NC + 255) / 256, 256>>>();
    pool_kernel<<<(NN * NC + 255) / 256, 256>>>(batch);
    mlp_kernel<<<NG, 64>>>(W1, b1, W2, b2, out);
}

// round 2
// speedup vs baseline: 1.0495x; 1.0495x over previous
#include <cuda_runtime.h>
#include <math.h>

#define NN 100000
#define NE 1200000
#define NC 64
#define NG 256
#define EPSBN 1e-5f

// ---------------- static scratch ----------------
__device__ float  d_h[NN * NC];
__device__ float  d_y[NN * NC];
__device__ float  d_A[NN * 2 * NC];
__device__ float  d_B[NN * 2 * NC];
__device__ int    d_cnt[NN];
__device__ int    d_fill[NN];
__device__ int    d_off[NN + 1];
__device__ int2   d_edge[NE];          // (src, ea bits) sorted by dst
__device__ double d_stats[2 * NC];
__device__ float  d_pool[NG * NC];
__device__ int    d_gcnt[NG];

// ---------------- f32x2 packed helpers ----------------
__device__ __forceinline__ unsigned long long pack2(float x, float y) {
    unsigned long long r;
    asm("mov.b64 %0, {%1, %2};" : "=l"(r) : "f"(x), "f"(y));
    return r;
}
__device__ __forceinline__ void unpack2(unsigned long long v, float& x, float& y) {
    asm("mov.b64 {%0, %1}, %2;" : "=f"(x), "=f"(y) : "l"(v));
}
__device__ __forceinline__ unsigned long long ffma2(unsigned long long a,
                                                    unsigned long long b,
                                                    unsigned long long c) {
    unsigned long long d;
    asm("fma.rn.f32x2 %0, %1, %2, %3;" : "=l"(d) : "l"(a), "l"(b), "l"(c));
    return d;
}

// ---------------- init ----------------
__global__ void init_kernel() {
    int i = blockIdx.x * blockDim.x + threadIdx.x;
    if (i < NN) { d_cnt[i] = 0; d_fill[i] = 0; }
    if (i < NG * NC) d_pool[i] = 0.f;
    if (i < NG) d_gcnt[i] = 0;
}

__global__ void hist_kernel(const int* __restrict__ ei, const int* __restrict__ batch) {
    int e = blockIdx.x * blockDim.x + threadIdx.x;
    if (e < NE) atomicAdd(&d_cnt[ei[NE + e]], 1);
    if (e < NN) atomicAdd(&d_gcnt[batch[e]], 1);
}

__global__ void scan_kernel() {
    const int CH = (NN + 1023) / 1024;
    int tid = threadIdx.x;
    int start = tid * CH;
    int end = min(start + CH, NN);
    int s = 0;
    for (int i = start; i < end; i++) s += d_cnt[i];

    __shared__ int warp_sums[32];
    int lane = tid & 31, w = tid >> 5;
    int incl = s;
    #pragma unroll
    for (int o = 1; o < 32; o <<= 1) {
        int t = __shfl_up_sync(0xffffffffu, incl, o);
        if (lane >= o) incl += t;
    }
    if (lane == 31) warp_sums[w] = incl;
    __syncthreads();
    if (w == 0) {
        int v = warp_sums[lane];
        #pragma unroll
        for (int o = 1; o < 32; o <<= 1) {
            int t = __shfl_up_sync(0xffffffffu, v, o);
            if (lane >= o) v += t;
        }
        warp_sums[lane] = v;
    }
    __syncthreads();
    int excl = incl - s + (w > 0 ? warp_sums[w - 1] : 0);
    int run = excl;
    for (int i = start; i < end; i++) { d_off[i] = run; run += d_cnt[i]; }
    if (tid == 1023) d_off[NN] = NE;
}

__global__ void scatter_kernel(const int* __restrict__ ei, const float* __restrict__ ea) {
    int e = blockIdx.x * blockDim.x + threadIdx.x;
    if (e < NE) {
        int d = ei[NE + e];
        int p = atomicAdd(&d_fill[d], 1);
        int idx = d_off[d] + p;
        d_edge[idx] = make_int2(ei[e], __float_as_int(ea[e]));
    }
}

__global__ void zero_stats_kernel() {
    int i = threadIdx.x;
    if (i < 2 * NC) d_stats[i] = 0.0;
}

// ---------------- fused BN prep+apply (+optional residual/relu/pool) ----------------
__global__ __launch_bounds__(256) void bn_apply_kernel(const float* __restrict__ g,
                                                       const float* __restrict__ beta,
                                                       const int* __restrict__ batch,
                                                       int residual, int relu, int dopool) {
    __shared__ float sscale[NC], sshift[NC];
    int tid = threadIdx.x;
    if (tid < NC) {
        double mu = d_stats[tid] / (double)NN;
        double var = d_stats[NC + tid] / (double)NN - mu * mu;
        float rs = rsqrtf((float)var + EPSBN);
        float sc = g[tid] * rs;
        sscale[tid] = sc;
        sshift[tid] = beta[tid] - (float)mu * sc;
    }
    __syncthreads();
    int idx = blockIdx.x * 256 + tid;
    if (idx >= NN * NC) return;
    int c = idx & 63;
    float v = fmaf(d_y[idx], sscale[c], sshift[c]);
    if (residual) v += d_h[idx];
    if (relu) v = fmaxf(v, 0.f);
    d_h[idx] = v;
    if (dopool) {
        int node = idx >> 6;
        atomicAdd(&d_pool[batch[node] * 64 + c], v);
    }
}

// ---------------- input layer ----------------
__global__ __launch_bounds__(256) void input_kernel(const float* __restrict__ x,
                                                    const float* __restrict__ W,
                                                    const float* __restrict__ b) {
    __shared__ float ws[12 * 64];
    __shared__ float xs[4 * 12];
    __shared__ float ssum[64], ssq[64];
    int tid = threadIdx.x;
    int base = blockIdx.x * 4;
    for (int i = tid; i < 12 * 64; i += 256) ws[i] = W[i];
    if (tid < 48) {
        int n = tid / 12, k = tid % 12;
        xs[tid] = (base + n < NN) ? x[(base + n) * 12 + k] : 0.f;
    }
    if (tid < 64) { ssum[tid] = 0.f; ssq[tid] = 0.f; }
    __syncthreads();
    int n = tid >> 6;
    int c = tid & 63;
    float acc = b[c];
    #pragma unroll
    for (int k = 0; k < 12; k++) acc = fmaf(xs[n * 12 + k], ws[k * 64 + c], acc);
    if (base + n < NN) {
        d_y[(size_t)(base + n) * 64 + c] = acc;
        atomicAdd(&ssum[c], acc);
        atomicAdd(&ssq[c], acc * acc);
    }
    __syncthreads();
    if (tid < 64) {
        atomicAdd(&d_stats[tid], (double)ssum[tid]);
        atomicAdd(&d_stats[64 + tid], (double)ssq[tid]);
    }
}

// ---------------- node projections (4 quadrants), conflict-free + f32x2 ----------------
__global__ __launch_bounds__(256) void gemm_AB_kernel(const float* __restrict__ Wf,
                                                      const float* __restrict__ Ws) {
    // blockIdx.y: 0: A/f, 1: A/s, 2: B/f, 3: B/s
    __shared__ float hsT[64][65];                 // [k][node], padded: conflict-free
    __shared__ __align__(16) float wsm[64][64];   // [k][col]
    int tid = threadIdx.x;
    int q = blockIdx.y;
    const float* Wbase = ((q == 0 || q == 2) ? Wf : Ws) + ((q >= 2) ? 64 * 64 : 0);
    int nb = blockIdx.x * 64;

    #pragma unroll
    for (int m = 0; m < 16; m++) {
        int lin = m * 256 + tid;
        int a = lin >> 6, bidx = lin & 63;
        float v = (nb + a < NN) ? d_h[(size_t)(nb + a) * 64 + bidx] : 0.f;
        hsT[bidx][a] = v;          // consecutive lanes -> consecutive banks (stride 65)
        wsm[a][bidx] = Wbase[lin];
    }
    __syncthreads();

    int tx = tid & 15, ty = tid >> 4;
    unsigned long long acc[4][2];
    #pragma unroll
    for (int r = 0; r < 4; r++) { acc[r][0] = pack2(0.f, 0.f); acc[r][1] = pack2(0.f, 0.f); }

    #pragma unroll
    for (int k = 0; k < 64; k++) {
        float4 bq = *(const float4*)&wsm[k][tx * 4];
        unsigned long long b01 = pack2(bq.x, bq.y);
        unsigned long long b23 = pack2(bq.z, bq.w);
        #pragma unroll
        for (int r = 0; r < 4; r++) {
            float a = hsT[k][ty * 4 + r];       // 2-way broadcast within warp
            unsigned long long aa = pack2(a, a);
            acc[r][0] = ffma2(aa, b01, acc[r][0]);
            acc[r][1] = ffma2(aa, b23, acc[r][1]);
        }
    }

    float* outp = (q < 2) ? d_A : d_B;
    int coff = (q & 1) ? 64 : 0;
    #pragma unroll
    for (int r = 0; r < 4; r++) {
        int n = nb + ty * 4 + r;
        if (n < NN) {
            float4 v;
            unpack2(acc[r][0], v.x, v.y);
            unpack2(acc[r][1], v.z, v.w);
            *(float4*)&outp[(size_t)n * 128 + coff + tx * 4] = v;
        }
    }
}

// ---------------- edge pass: warp per dst node, 2x unrolled ----------------
__global__ __launch_bounds__(256) void edge_agg_kernel(const float* __restrict__ Wf,
                                                       const float* __restrict__ bf,
                                                       const float* __restrict__ Ws,
                                                       const float* __restrict__ bs) {
    __shared__ float ssum[64], ssq[64];
    int tid = threadIdx.x;
    if (tid < 64) { ssum[tid] = 0.f; ssq[tid] = 0.f; }
    __syncthreads();

    int lane = tid & 31, w = tid >> 5;
    int node = blockIdx.x * 8 + w;
    if (node < NN) {
        int c0 = lane, c1 = lane + 32;
        const float* Ap = d_A + (size_t)node * 128;
        float af0 = Ap[c0], af1 = Ap[c1], as0 = Ap[64 + c0], as1 = Ap[64 + c1];
        float wf0 = Wf[128 * 64 + c0], wf1 = Wf[128 * 64 + c1];
        float ws0 = Ws[128 * 64 + c0], ws1 = Ws[128 * 64 + c1];
        float vbf0 = bf[c0], vbf1 = bf[c1], vbs0 = bs[c0], vbs1 = bs[c1];
        float acc0 = 0.f, acc1 = 0.f;
        int e0 = d_off[node], e1 = d_off[node + 1];

        #define EDGE_BODY(Bp, ea)                                                 \
        {                                                                         \
            float tf0 = af0 + (Bp)[c0]      + fmaf((ea), wf0, vbf0);              \
            float tf1 = af1 + (Bp)[c1]      + fmaf((ea), wf1, vbf1);              \
            float ts0 = as0 + (Bp)[64 + c0] + fmaf((ea), ws0, vbs0);              \
            float ts1 = as1 + (Bp)[64 + c1] + fmaf((ea), ws1, vbs1);              \
            float sg0 = __fdividef(1.f, 1.f + __expf(-tf0));                      \
            float sg1 = __fdividef(1.f, 1.f + __expf(-tf1));                      \
            float sp0 = fmaxf(ts0, 0.f) + __logf(1.f + __expf(-fabsf(ts0)));      \
            float sp1 = fmaxf(ts1, 0.f) + __logf(1.f + __expf(-fabsf(ts1)));      \
            acc0 = fmaf(sg0, sp0, acc0);                                          \
            acc1 = fmaf(sg1, sp1, acc1);                                          \
        }

        int e = e0;
        for (; e + 1 < e1; e += 2) {
            int2 p0 = d_edge[e];
            int2 p1 = d_edge[e + 1];
            const float* B0 = d_B + (size_t)p0.x * 128;
            const float* B1 = d_B + (size_t)p1.x * 128;
            float ea0 = __int_as_float(p0.y);
            float ea1 = __int_as_float(p1.y);
            EDGE_BODY(B0, ea0)
            EDGE_BODY(B1, ea1)
        }
        if (e < e1) {
            int2 p0 = d_edge[e];
            const float* B0 = d_B + (size_t)p0.x * 128;
            float ea0 = __int_as_float(p0.y);
            EDGE_BODY(B0, ea0)
        }
        #undef EDGE_BODY

        d_y[(size_t)node * 64 + c0] = acc0;
        d_y[(size_t)node * 64 + c1] = acc1;
        atomicAdd(&ssum[c0], acc0); atomicAdd(&ssq[c0], acc0 * acc0);
        atomicAdd(&ssum[c1], acc1); atomicAdd(&ssq[c1], acc1 * acc1);
    }
    __syncthreads();
    if (tid < 64) {
        atomicAdd(&d_stats[tid], (double)ssum[tid]);
        atomicAdd(&d_stats[64 + tid], (double)ssq[tid]);
    }
}

// ---------------- final MLP ----------------
__global__ void mlp_kernel(const float* __restrict__ W1, const float* __restrict__ b1,
                           const float* __restrict__ W2, const float* __restrict__ b2,
                           float* __restrict__ out) {
    __shared__ float p[64];
    __shared__ float h1[32];
    int g = blockIdx.x;
    int tid = threadIdx.x;
    float inv = 1.f / fmaxf((float)d_gcnt[g], 1.f);
    p[tid] = d_pool[g * 64 + tid] * inv;
    __syncthreads();
    if (tid < 32) {
        float a = b1[tid];
        #pragma unroll
        for (int k = 0; k < 64; k++) a = fmaf(p[k], W1[k * 32 + tid], a);
        h1[tid] = fmaxf(a, 0.f);
    }
    __syncthreads();
    if (tid < 32) {
        float v = h1[tid] * W2[tid];
        #pragma unroll
        for (int o = 16; o > 0; o >>= 1) v += __shfl_down_sync(0xffffffffu, v, o);
        if (tid == 0) out[g] = v + b2[0];
    }
}

// ---------------- launcher ----------------
extern "C" void kernel_launch(void* const* d_in, const int* in_sizes, int n_in,
                              void* d_out, int out_size) {
    const float* x     = (const float*)d_in[0];
    const int*   ei    = (const int*)d_in[1];
    const float* ea    = (const float*)d_in[2];
    const int*   batch = (const int*)d_in[3];
    const float* W_in  = (const float*)d_in[4];
    const float* b_in  = (const float*)d_in[5];
    const float* g0    = (const float*)d_in[6];
    const float* beta0 = (const float*)d_in[7];
    const float* Wf[3] = {(const float*)d_in[8],  (const float*)d_in[14], (const float*)d_in[20]};
    const float* bf[3] = {(const float*)d_in[9],  (const float*)d_in[15], (const float*)d_in[21]};
    const float* Ws[3] = {(const float*)d_in[10], (const float*)d_in[16], (const float*)d_in[22]};
    const float* bs[3] = {(const float*)d_in[11], (const float*)d_in[17], (const float*)d_in[23]};
    const float* gg[3] = {(const float*)d_in[12], (const float*)d_in[18], (const float*)d_in[24]};
    const float* bb[3] = {(const float*)d_in[13], (const float*)d_in[19], (const float*)d_in[25]};
    const float* W1 = (const float*)d_in[26];
    const float* b1 = (const float*)d_in[27];
    const float* W2 = (const float*)d_in[28];
    const float* b2 = (const float*)d_in[29];
    float* out = (float*)d_out;

    init_kernel<<<(NN + 255) / 256, 256>>>();
    hist_kernel<<<(NE + 255) / 256, 256>>>(ei, batch);
    scan_kernel<<<1, 1024>>>();
    scatter_kernel<<<(NE + 255) / 256, 256>>>(ei, ea);

    zero_stats_kernel<<<1, 128>>>();
    input_kernel<<<(NN + 3) / 4, 256>>>(x, W_in, b_in);
    bn_apply_kernel<<<(NN * NC + 255) / 256, 256>>>(g0, beta0, batch, 0, 1, 0);

    for (int l = 0; l < 3; l++) {
        gemm_AB_kernel<<<dim3((NN + 63) / 64, 4), 256>>>(Wf[l], Ws[l]);
        zero_stats_kernel<<<1, 128>>>();
        edge_agg_kernel<<<(NN + 7) / 8, 256>>>(Wf[l], bf[l], Ws[l], bs[l]);
        bn_apply_kernel<<<(NN * NC + 255) / 256, 256>>>(gg[l], bb[l], batch,
                                                        1, (l < 2) ? 1 : 0, (l == 2) ? 1 : 0);
    }

    mlp_kernel<<<NG, 64>>>(W1, b1, W2, b2, out);
}

// round 5
// speedup vs baseline: 1.1040x; 1.0520x over previous
#include <cuda_runtime.h>
#include <math.h>

#define NN 100000
#define NE 1200000
#define NC 64
#define NG 256
#define EPSBN 1e-5f

// ---------------- static scratch ----------------
__device__ float  d_h[NN * NC];
__device__ float  d_y[NN * NC];
__device__ float  d_A[NN * 2 * NC];    // [Af(64) | As(64)] per node
__device__ float  d_B[NN * 2 * NC];    // interleaved: (f[c], s[c]) pairs per node
__device__ int    d_cnt[NN];
__device__ int    d_fill[NN];
__device__ int    d_off[NN + 1];
__device__ int2   d_edge[NE];          // (src, ea bits) sorted by dst
__device__ double d_stats[2 * NC];
__device__ float  d_bnscale[NC];
__device__ float  d_bnshift[NC];
__device__ float  d_pool[NG * NC];
__device__ int    d_gcnt[NG];

// ---------------- helpers ----------------
__device__ __forceinline__ unsigned long long pack2(float x, float y) {
    unsigned long long r;
    asm("mov.b64 %0, {%1, %2};" : "=l"(r) : "f"(x), "f"(y));
    return r;
}
__device__ __forceinline__ void unpack2(unsigned long long v, float& x, float& y) {
    asm("mov.b64 {%0, %1}, %2;" : "=f"(x), "=f"(y) : "l"(v));
}
__device__ __forceinline__ unsigned long long ffma2(unsigned long long a,
                                                    unsigned long long b,
                                                    unsigned long long c) {
    unsigned long long d;
    asm("fma.rn.f32x2 %0, %1, %2, %3;" : "=l"(d) : "l"(a), "l"(b), "l"(c));
    return d;
}
__device__ __forceinline__ float sigmoid_t(float x) {
    float t;
    asm("tanh.approx.f32 %0, %1;" : "=f"(t) : "f"(0.5f * x));
    return fmaf(0.5f, t, 0.5f);
}
__device__ __forceinline__ float softplus_f(float x) {
    return fmaxf(x, 0.f) + __logf(1.f + __expf(-fabsf(x)));
}

// ---------------- init ----------------
__global__ void init_kernel() {
    int i = blockIdx.x * blockDim.x + threadIdx.x;
    if (i < NN) { d_cnt[i] = 0; d_fill[i] = 0; }
    if (i < NG * NC) d_pool[i] = 0.f;
    if (i < NG) d_gcnt[i] = 0;
    if (i < 2 * NC) d_stats[i] = 0.0;
}

__global__ void hist_kernel(const int* __restrict__ ei, const int* __restrict__ batch) {
    int e = blockIdx.x * blockDim.x + threadIdx.x;
    if (e < NE) atomicAdd(&d_cnt[ei[NE + e]], 1);
    if (e < NN) atomicAdd(&d_gcnt[batch[e]], 1);
}

__global__ void scan_kernel() {
    const int CH = (NN + 1023) / 1024;
    int tid = threadIdx.x;
    int start = tid * CH;
    int end = min(start + CH, NN);
    int s = 0;
    for (int i = start; i < end; i++) s += d_cnt[i];

    __shared__ int warp_sums[32];
    int lane = tid & 31, w = tid >> 5;
    int incl = s;
    #pragma unroll
    for (int o = 1; o < 32; o <<= 1) {
        int t = __shfl_up_sync(0xffffffffu, incl, o);
        if (lane >= o) incl += t;
    }
    if (lane == 31) warp_sums[w] = incl;
    __syncthreads();
    if (w == 0) {
        int v = warp_sums[lane];
        #pragma unroll
        for (int o = 1; o < 32; o <<= 1) {
            int t = __shfl_up_sync(0xffffffffu, v, o);
            if (lane >= o) v += t;
        }
        warp_sums[lane] = v;
    }
    __syncthreads();
    int excl = incl - s + (w > 0 ? warp_sums[w - 1] : 0);
    int run = excl;
    for (int i = start; i < end; i++) { d_off[i] = run; run += d_cnt[i]; }
    if (tid == 1023) d_off[NN] = NE;
}

__global__ void scatter_kernel(const int* __restrict__ ei, const float* __restrict__ ea) {
    int e = blockIdx.x * blockDim.x + threadIdx.x;
    if (e < NE) {
        int d = ei[NE + e];
        int p = atomicAdd(&d_fill[d], 1);
        d_edge[d_off[d] + p] = make_int2(ei[e], __float_as_int(ea[e]));
    }
}

// ---------------- BN prep: one tiny kernel, fp32 results, zeroes stats ----------------
__global__ void bn_prep_kernel(const float* __restrict__ g, const float* __restrict__ beta) {
    int c = threadIdx.x;
    if (c < NC) {
        double mu = d_stats[c] * (1.0 / (double)NN);
        double var = d_stats[NC + c] * (1.0 / (double)NN) - mu * mu;
        float rs = rsqrtf((float)var + EPSBN);
        float sc = g[c] * rs;
        d_bnscale[c] = sc;
        d_bnshift[c] = beta[c] - (float)mu * sc;
        d_stats[c] = 0.0;
        d_stats[NC + c] = 0.0;
    }
}

// ---------------- BN apply: pure fp32 stream ----------------
__global__ __launch_bounds__(256) void bn_apply_kernel(const int* __restrict__ batch,
                                                       int residual, int relu, int dopool) {
    int idx = blockIdx.x * 256 + threadIdx.x;
    if (idx >= NN * NC) return;
    int c = idx & 63;
    float v = fmaf(d_y[idx], d_bnscale[c], d_bnshift[c]);
    if (residual) v += d_h[idx];
    if (relu) v = fmaxf(v, 0.f);
    d_h[idx] = v;
    if (dopool) {
        int node = idx >> 6;
        atomicAdd(&d_pool[batch[node] * 64 + c], v);
    }
}

// ---------------- input layer: 64 nodes per block ----------------
__global__ __launch_bounds__(256) void input_kernel(const float* __restrict__ x,
                                                    const float* __restrict__ W,
                                                    const float* __restrict__ b) {
    __shared__ float ws[12 * 64];
    __shared__ float xs[64 * 12];
    __shared__ float ssum[64], ssq[64];
    int tid = threadIdx.x;
    int base = blockIdx.x * 64;
    for (int i = tid; i < 12 * 64; i += 256) ws[i] = W[i];
    for (int i = tid; i < 64 * 12; i += 256) {
        int n = i / 12;
        xs[i] = (base + n < NN) ? x[(size_t)(base + n) * 12 + (i % 12)] : 0.f;
    }
    if (tid < 64) { ssum[tid] = 0.f; ssq[tid] = 0.f; }
    __syncthreads();
    int c = tid & 63;
    float bc = b[c];
    float lsum = 0.f, lsq = 0.f;
    #pragma unroll
    for (int p = 0; p < 16; p++) {
        int n = p * 4 + (tid >> 6);
        float acc = bc;
        #pragma unroll
        for (int k = 0; k < 12; k++) acc = fmaf(xs[n * 12 + k], ws[k * 64 + c], acc);
        if (base + n < NN) {
            d_y[(size_t)(base + n) * 64 + c] = acc;
            lsum += acc;
            lsq = fmaf(acc, acc, lsq);
        }
    }
    atomicAdd(&ssum[c], lsum);
    atomicAdd(&ssq[c], lsq);
    __syncthreads();
    if (tid < 64) {
        atomicAdd(&d_stats[tid], (double)ssum[tid]);
        atomicAdd(&d_stats[64 + tid], (double)ssq[tid]);
    }
}

// ---------------- node projections ----------------
__global__ __launch_bounds__(256) void gemm_AB_kernel(const float* __restrict__ Wf,
                                                      const float* __restrict__ Ws) {
    // blockIdx.y: 0: A/f, 1: A/s, 2: B/f, 3: B/s
    __shared__ float hsT[64][65];
    __shared__ __align__(16) float wsm[64][64];
    int tid = threadIdx.x;
    int q = blockIdx.y;
    const float* Wbase = ((q == 0 || q == 2) ? Wf : Ws) + ((q >= 2) ? 64 * 64 : 0);
    int nb = blockIdx.x * 64;

    #pragma unroll
    for (int m = 0; m < 16; m++) {
        int lin = m * 256 + tid;
        int a = lin >> 6, bidx = lin & 63;
        float v = (nb + a < NN) ? d_h[(size_t)(nb + a) * 64 + bidx] : 0.f;
        hsT[bidx][a] = v;
        wsm[a][bidx] = Wbase[lin];
    }
    __syncthreads();

    int tx = tid & 15, ty = tid >> 4;
    unsigned long long acc[4][2];
    #pragma unroll
    for (int r = 0; r < 4; r++) { acc[r][0] = pack2(0.f, 0.f); acc[r][1] = pack2(0.f, 0.f); }

    #pragma unroll
    for (int k = 0; k < 64; k++) {
        float4 bq = *(const float4*)&wsm[k][tx * 4];
        unsigned long long b01 = pack2(bq.x, bq.y);
        unsigned long long b23 = pack2(bq.z, bq.w);
        #pragma unroll
        for (int r = 0; r < 4; r++) {
            float a = hsT[k][ty * 4 + r];
            unsigned long long aa = pack2(a, a);
            acc[r][0] = ffma2(aa, b01, acc[r][0]);
            acc[r][1] = ffma2(aa, b23, acc[r][1]);
        }
    }

    #pragma unroll
    for (int r = 0; r < 4; r++) {
        int n = nb + ty * 4 + r;
        if (n < NN) {
            float4 v;
            unpack2(acc[r][0], v.x, v.y);
            unpack2(acc[r][1], v.z, v.w);
            if (q < 2) {
                int coff = (q & 1) ? 64 : 0;
                *(float4*)&d_A[(size_t)n * 128 + coff + tx * 4] = v;
            } else {
                // interleaved (f,s) pairs: f at even slot, s at odd slot
                float* Bp = d_B + (size_t)n * 128 + (q & 1);
                Bp[(tx * 4 + 0) * 2] = v.x;
                Bp[(tx * 4 + 1) * 2] = v.y;
                Bp[(tx * 4 + 2) * 2] = v.z;
                Bp[(tx * 4 + 3) * 2] = v.w;
            }
        }
    }
}

// ---------------- edge pass: warp per dst node, float2 gathers, 4x unroll ----------------
__global__ __launch_bounds__(256) void edge_agg_kernel(const float* __restrict__ Wf,
                                                       const float* __restrict__ bf,
                                                       const float* __restrict__ Ws,
                                                       const float* __restrict__ bs) {
    __shared__ float ssum[64], ssq[64];
    int tid = threadIdx.x;
    if (tid < 64) { ssum[tid] = 0.f; ssq[tid] = 0.f; }
    __syncthreads();

    int lane = tid & 31, w = tid >> 5;
    int node = blockIdx.x * 8 + w;
    if (node < NN) {
        int c0 = lane, c1 = lane + 32;
        const float* Ap = d_A + (size_t)node * 128;
        float af0 = Ap[c0], af1 = Ap[c1], as0 = Ap[64 + c0], as1 = Ap[64 + c1];
        float wf0 = Wf[128 * 64 + c0], wf1 = Wf[128 * 64 + c1];
        float ws0 = Ws[128 * 64 + c0], ws1 = Ws[128 * 64 + c1];
        float vbf0 = bf[c0], vbf1 = bf[c1], vbs0 = bs[c0], vbs1 = bs[c1];
        float acc0 = 0.f, acc1 = 0.f;
        int e0 = d_off[node], e1 = d_off[node + 1];

        #define EDGE_BODY(p)                                                       \
        {                                                                          \
            const float2* Bp2 = (const float2*)(d_B + (size_t)(p).x * 128);        \
            float ea = __int_as_float((p).y);                                      \
            float2 bv0 = Bp2[c0];                                                  \
            float2 bv1 = Bp2[c1];                                                  \
            float tf0 = af0 + bv0.x + fmaf(ea, wf0, vbf0);                         \
            float ts0 = as0 + bv0.y + fmaf(ea, ws0, vbs0);                         \
            float tf1 = af1 + bv1.x + fmaf(ea, wf1, vbf1);                         \
            float ts1 = as1 + bv1.y + fmaf(ea, ws1, vbs1);                         \
            float sg0 = sigmoid_t(tf0);                                            \
            float sg1 = sigmoid_t(tf1);                                            \
            float sp0 = softplus_f(ts0);                                           \
            float sp1 = softplus_f(ts1);                                           \
            acc0 = fmaf(sg0, sp0, acc0);                                           \
            acc1 = fmaf(sg1, sp1, acc1);                                           \
        }

        int e = e0;
        for (; e + 3 < e1; e += 4) {
            int2 p0 = d_edge[e];
            int2 p1 = d_edge[e + 1];
            int2 p2 = d_edge[e + 2];
            int2 p3 = d_edge[e + 3];
            EDGE_BODY(p0) EDGE_BODY(p1) EDGE_BODY(p2) EDGE_BODY(p3)
        }
        for (; e < e1; e++) {
            int2 p0 = d_edge[e];
            EDGE_BODY(p0)
        }
        #undef EDGE_BODY

        d_y[(size_t)node * 64 + c0] = acc0;
        d_y[(size_t)node * 64 + c1] = acc1;
        atomicAdd(&ssum[c0], acc0); atomicAdd(&ssq[c0], acc0 * acc0);
        atomicAdd(&ssum[c1], acc1); atomicAdd(&ssq[c1], acc1 * acc1);
    }
    __syncthreads();
    if (tid < 64) {
        atomicAdd(&d_stats[tid], (double)ssum[tid]);
        atomicAdd(&d_stats[64 + tid], (double)ssq[tid]);
    }
}

// ---------------- final MLP ----------------
__global__ void mlp_kernel(const float* __restrict__ W1, const float* __restrict__ b1,
                           const float* __restrict__ W2, const float* __restrict__ b2,
                           float* __restrict__ out) {
    __shared__ float p[64];
    __shared__ float h1[32];
    int g = blockIdx.x;
    int tid = threadIdx.x;
    float inv = 1.f / fmaxf((float)d_gcnt[g], 1.f);
    p[tid] = d_pool[g * 64 + tid] * inv;
    __syncthreads();
    if (tid < 32) {
        float a = b1[tid];
        #pragma unroll
        for (int k = 0; k < 64; k++) a = fmaf(p[k], W1[k * 32 + tid], a);
        h1[tid] = fmaxf(a, 0.f);
    }
    __syncthreads();
    if (tid < 32) {
        float v = h1[tid] * W2[tid];
        #pragma unroll
        for (int o = 16; o > 0; o >>= 1) v += __shfl_down_sync(0xffffffffu, v, o);
        if (tid == 0) out[g] = v + b2[0];
    }
}

// ---------------- launcher ----------------
extern "C" void kernel_launch(void* const* d_in, const int* in_sizes, int n_in,
                              void* d_out, int out_size) {
    const float* x     = (const float*)d_in[0];
    const int*   ei    = (const int*)d_in[1];
    const float* ea    = (const float*)d_in[2];
    const int*   batch = (const int*)d_in[3];
    const float* W_in  = (const float*)d_in[4];
    const float* b_in  = (const float*)d_in[5];
    const float* g0    = (const float*)d_in[6];
    const float* beta0 = (const float*)d_in[7];
    const float* Wf[3] = {(const float*)d_in[8],  (const float*)d_in[14], (const float*)d_in[20]};
    const float* bf[3] = {(const float*)d_in[9],  (const float*)d_in[15], (const float*)d_in[21]};
    const float* Ws[3] = {(const float*)d_in[10], (const float*)d_in[16], (const float*)d_in[22]};
    const float* bs[3] = {(const float*)d_in[11], (const float*)d_in[17], (const float*)d_in[23]};
    const float* gg[3] = {(const float*)d_in[12], (const float*)d_in[18], (const float*)d_in[24]};
    const float* bb[3] = {(const float*)d_in[13], (const float*)d_in[19], (const float*)d_in[25]};
    const float* W1 = (const float*)d_in[26];
    const float* b1 = (const float*)d_in[27];
    const float* W2 = (const float*)d_in[28];
    const float* b2 = (const float*)d_in[29];
    float* out = (float*)d_out;

    init_kernel<<<(NN + 255) / 256, 256>>>();
    hist_kernel<<<(NE + 255) / 256, 256>>>(ei, batch);
    scan_kernel<<<1, 1024>>>();
    scatter_kernel<<<(NE + 255) / 256, 256>>>(ei, ea);

    input_kernel<<<(NN + 63) / 64, 256>>>(x, W_in, b_in);
    bn_prep_kernel<<<1, 64>>>(g0, beta0);
    bn_apply_kernel<<<(NN * NC + 255) / 256, 256>>>(batch, 0, 1, 0);

    for (int l = 0; l < 3; l++) {
        gemm_AB_kernel<<<dim3((NN + 63) / 64, 4), 256>>>(Wf[l], Ws[l]);
        edge_agg_kernel<<<(NN + 7) / 8, 256>>>(Wf[l], bf[l], Ws[l], bs[l]);
        bn_prep_kernel<<<1, 64>>>(gg[l], bb[l]);
        bn_apply_kernel<<<(NN * NC + 255) / 256, 256>>>(batch, 1, (l < 2) ? 1 : 0,
                                                        (l == 2) ? 1 : 0);
    }

    mlp_kernel<<<NG, 64>>>(W1, b1, W2, b2, out);
}

// round 7
// speedup vs baseline: 1.4380x; 1.3026x over previous
#include <cuda_runtime.h>
#include <cuda_bf16.h>
#include <math.h>

#define NN 100000
#define NE 1200000
#define NC 64
#define NG 256
#define EPSBN 1e-5f

// ---------------- static scratch ----------------
__device__ float        d_h[NN * NC];
__device__ float        d_y[NN * NC];
__device__ float        d_A[NN * 2 * NC];   // [Af(64) | As(64)] per node, fp32
__device__ unsigned int d_Bb[NN * NC];      // per node, per channel: bf16x2 (hi=f, lo=s)
__device__ int          d_cnt[NN];
__device__ int          d_fill[NN];
__device__ int          d_off[NN + 1];
__device__ int2         d_edge[NE];         // (src, ea bits) sorted by dst
__device__ double       d_stats[2 * NC];
__device__ float        d_bnscale[NC];
__device__ float        d_bnshift[NC];
__device__ float        d_pool[NG * NC];
__device__ int          d_gcnt[NG];

// ---------------- helpers ----------------
__device__ __forceinline__ unsigned long long pack2(float x, float y) {
    unsigned long long r;
    asm("mov.b64 %0, {%1, %2};" : "=l"(r) : "f"(x), "f"(y));
    return r;
}
__device__ __forceinline__ void unpack2(unsigned long long v, float& x, float& y) {
    asm("mov.b64 {%0, %1}, %2;" : "=f"(x), "=f"(y) : "l"(v));
}
__device__ __forceinline__ unsigned long long ffma2(unsigned long long a,
                                                    unsigned long long b,
                                                    unsigned long long c) {
    unsigned long long d;
    asm("fma.rn.f32x2 %0, %1, %2, %3;" : "=l"(d) : "l"(a), "l"(b), "l"(c));
    return d;
}
__device__ __forceinline__ float sigmoid_t(float x) {
    float t;
    asm("tanh.approx.f32 %0, %1;" : "=f"(t) : "f"(0.5f * x));
    return fmaf(0.5f, t, 0.5f);
}
__device__ __forceinline__ float softplus_f(float x) {
    return fmaxf(x, 0.f) + __logf(1.f + __expf(-fabsf(x)));
}
// pack (f -> high 16, s -> low 16)
__device__ __forceinline__ unsigned int packfs(float f, float s) {
    __nv_bfloat162 h2 = __floats2bfloat162_rn(s, f);   // .x (low) = s, .y (high) = f
    return *reinterpret_cast<unsigned int*>(&h2);
}

// ---------------- init ----------------
__global__ void init_kernel() {
    int i = blockIdx.x * blockDim.x + threadIdx.x;
    if (i < NN) { d_cnt[i] = 0; d_fill[i] = 0; }
    if (i < NG * NC) d_pool[i] = 0.f;
    if (i < NG) d_gcnt[i] = 0;
    if (i < 2 * NC) d_stats[i] = 0.0;
}

__global__ void hist_kernel(const int* __restrict__ ei, const int* __restrict__ batch) {
    int e = blockIdx.x * blockDim.x + threadIdx.x;
    if (e < NE) atomicAdd(&d_cnt[ei[NE + e]], 1);
    if (e < NN) atomicAdd(&d_gcnt[batch[e]], 1);
}

__global__ void scan_kernel() {
    const int CH = (NN + 1023) / 1024;
    int tid = threadIdx.x;
    int start = tid * CH;
    int end = min(start + CH, NN);
    int s = 0;
    for (int i = start; i < end; i++) s += d_cnt[i];

    __shared__ int warp_sums[32];
    int lane = tid & 31, w = tid >> 5;
    int incl = s;
    #pragma unroll
    for (int o = 1; o < 32; o <<= 1) {
        int t = __shfl_up_sync(0xffffffffu, incl, o);
        if (lane >= o) incl += t;
    }
    if (lane == 31) warp_sums[w] = incl;
    __syncthreads();
    if (w == 0) {
        int v = warp_sums[lane];
        #pragma unroll
        for (int o = 1; o < 32; o <<= 1) {
            int t = __shfl_up_sync(0xffffffffu, v, o);
            if (lane >= o) v += t;
        }
        warp_sums[lane] = v;
    }
    __syncthreads();
    int excl = incl - s + (w > 0 ? warp_sums[w - 1] : 0);
    int run = excl;
    for (int i = start; i < end; i++) { d_off[i] = run; run += d_cnt[i]; }
    if (tid == 1023) d_off[NN] = NE;
}

__global__ void scatter_kernel(const int* __restrict__ ei, const float* __restrict__ ea) {
    int e = blockIdx.x * blockDim.x + threadIdx.x;
    if (e < NE) {
        int d = ei[NE + e];
        int p = atomicAdd(&d_fill[d], 1);
        d_edge[d_off[d] + p] = make_int2(ei[e], __float_as_int(ea[e]));
    }
}

// ---------------- BN prep ----------------
__global__ void bn_prep_kernel(const float* __restrict__ g, const float* __restrict__ beta) {
    int c = threadIdx.x;
    if (c < NC) {
        double mu = d_stats[c] * (1.0 / (double)NN);
        double var = d_stats[NC + c] * (1.0 / (double)NN) - mu * mu;
        float rs = rsqrtf((float)var + EPSBN);
        float sc = g[c] * rs;
        d_bnscale[c] = sc;
        d_bnshift[c] = beta[c] - (float)mu * sc;
        d_stats[c] = 0.0;
        d_stats[NC + c] = 0.0;
    }
}

// ---------------- BN apply (no pooling) ----------------
__global__ __launch_bounds__(256) void bn_apply_kernel(int residual, int relu) {
    int idx = blockIdx.x * 256 + threadIdx.x;
    if (idx >= NN * NC) return;
    int c = idx & 63;
    float v = fmaf(d_y[idx], d_bnscale[c], d_bnshift[c]);
    if (residual) v += d_h[idx];
    if (relu) v = fmaxf(v, 0.f);
    d_h[idx] = v;
}

// ---------------- BN apply + pooled (last layer, batch sorted) ----------------
__global__ __launch_bounds__(1024) void bn_pool_kernel(const int* __restrict__ batch) {
    __shared__ float psum[64];
    __shared__ int sg[2];
    int tid = threadIdx.x;
    int idx = blockIdx.x * 1024 + tid;     // NN*NC == 6250*1024 exactly
    int node = idx >> 6;
    int c = idx & 63;
    float v = fmaf(d_y[idx], d_bnscale[c], d_bnshift[c]) + d_h[idx];
    d_h[idx] = v;
    int g = batch[node];
    if (tid == 0)    sg[0] = g;
    if (tid == 1023) sg[1] = g;
    __syncthreads();
    int g0 = sg[0], g1 = sg[1];
    for (int gg = g0; gg <= g1; gg++) {
        if (tid < 64) psum[tid] = 0.f;
        __syncthreads();
        if (g == gg) atomicAdd(&psum[c], v);
        __syncthreads();
        if (tid < 64 && psum[tid] != 0.f) atomicAdd(&d_pool[gg * 64 + tid], psum[tid]);
        __syncthreads();
    }
}

// ---------------- input layer ----------------
__global__ __launch_bounds__(256) void input_kernel(const float* __restrict__ x,
                                                    const float* __restrict__ W,
                                                    const float* __restrict__ b) {
    __shared__ float ws[12 * 64];
    __shared__ float xs[64 * 12];
    __shared__ float ssum[64], ssq[64];
    int tid = threadIdx.x;
    int base = blockIdx.x * 64;
    for (int i = tid; i < 12 * 64; i += 256) ws[i] = W[i];
    for (int i = tid; i < 64 * 12; i += 256) {
        int n = i / 12;
        xs[i] = (base + n < NN) ? x[(size_t)(base + n) * 12 + (i % 12)] : 0.f;
    }
    if (tid < 64) { ssum[tid] = 0.f; ssq[tid] = 0.f; }
    __syncthreads();
    int c = tid & 63;
    float bc = b[c];
    float lsum = 0.f, lsq = 0.f;
    #pragma unroll
    for (int p = 0; p < 16; p++) {
        int n = p * 4 + (tid >> 6);
        float acc = bc;
        #pragma unroll
        for (int k = 0; k < 12; k++) acc = fmaf(xs[n * 12 + k], ws[k * 64 + c], acc);
        if (base + n < NN) {
            d_y[(size_t)(base + n) * 64 + c] = acc;
            lsum += acc;
            lsq = fmaf(acc, acc, lsq);
        }
    }
    atomicAdd(&ssum[c], lsum);
    atomicAdd(&ssq[c], lsq);
    __syncthreads();
    if (tid < 64) {
        atomicAdd(&d_stats[tid], (double)ssum[tid]);
        atomicAdd(&d_stats[64 + tid], (double)ssq[tid]);
    }
}

// ---------------- node projections: 128-node tile, f+s fused ----------------
// blockIdx.y = 0 -> A side (W rows 0..63, fp32 out to d_A)
// blockIdx.y = 1 -> B side (W rows 64..127, bf16x2 out to d_Bb)
__global__ __launch_bounds__(256) void gemm_AB_kernel(const float* __restrict__ Wf,
                                                      const float* __restrict__ Ws) {
    __shared__ float hsT[64][129];                // [k][node]
    __shared__ __align__(16) float wsm[2][64][64]; // [f/s][k][col]
    int tid = threadIdx.x;
    int side = blockIdx.y;
    int nb = blockIdx.x * 128;
    const float* WfB = Wf + side * 64 * 64;
    const float* WsB = Ws + side * 64 * 64;

    #pragma unroll
    for (int m = 0; m < 32; m++) {
        int lin = m * 256 + tid;                  // 8192 elems
        int a = lin >> 6, k = lin & 63;
        hsT[k][a] = (nb + a < NN) ? d_h[(size_t)(nb + a) * 64 + k] : 0.f;
    }
    #pragma unroll
    for (int m = 0; m < 16; m++) {
        int lin = m * 256 + tid;                  // 4096 per tile
        int k = lin >> 6, c = lin & 63;
        wsm[0][k][c] = WfB[lin];
        wsm[1][k][c] = WsB[lin];
    }
    __syncthreads();

    int tx = tid & 7;          // 8 col-groups of 8
    int ty = tid >> 3;         // 32 row-groups of 4
    unsigned long long accF[4][4], accS[4][4];
    #pragma unroll
    for (int r = 0; r < 4; r++)
        #pragma unroll
        for (int j = 0; j < 4; j++) { accF[r][j] = 0ull; accS[r][j] = 0ull; }

    #pragma unroll
    for (int k = 0; k < 64; k++) {
        float4 f0 = *(const float4*)&wsm[0][k][tx * 8];
        float4 f1 = *(const float4*)&wsm[0][k][tx * 8 + 4];
        float4 s0 = *(const float4*)&wsm[1][k][tx * 8];
        float4 s1 = *(const float4*)&wsm[1][k][tx * 8 + 4];
        unsigned long long bf[4] = {pack2(f0.x, f0.y), pack2(f0.z, f0.w),
                                    pack2(f1.x, f1.y), pack2(f1.z, f1.w)};
        unsigned long long bs[4] = {pack2(s0.x, s0.y), pack2(s0.z, s0.w),
                                    pack2(s1.x, s1.y), pack2(s1.z, s1.w)};
        #pragma unroll
        for (int r = 0; r < 4; r++) {
            float a = hsT[k][ty * 4 + r];
            unsigned long long aa = pack2(a, a);
            #pragma unroll
            for (int j = 0; j < 4; j++) {
                accF[r][j] = ffma2(aa, bf[j], accF[r][j]);
                accS[r][j] = ffma2(aa, bs[j], accS[r][j]);
            }
        }
    }

    #pragma unroll
    for (int r = 0; r < 4; r++) {
        int n = nb + ty * 4 + r;
        if (n >= NN) continue;
        float fv[8], sv[8];
        #pragma unroll
        for (int j = 0; j < 4; j++) {
            unpack2(accF[r][j], fv[j * 2], fv[j * 2 + 1]);
            unpack2(accS[r][j], sv[j * 2], sv[j * 2 + 1]);
        }
        if (side == 0) {
            float4 v0 = make_float4(fv[0], fv[1], fv[2], fv[3]);
            float4 v1 = make_float4(fv[4], fv[5], fv[6], fv[7]);
            float4 v2 = make_float4(sv[0], sv[1], sv[2], sv[3]);
            float4 v3 = make_float4(sv[4], sv[5], sv[6], sv[7]);
            *(float4*)&d_A[(size_t)n * 128 + tx * 8]      = v0;
            *(float4*)&d_A[(size_t)n * 128 + tx * 8 + 4]  = v1;
            *(float4*)&d_A[(size_t)n * 128 + 64 + tx * 8]     = v2;
            *(float4*)&d_A[(size_t)n * 128 + 64 + tx * 8 + 4] = v3;
        } else {
            uint4 w0, w1;
            w0.x = packfs(fv[0], sv[0]); w0.y = packfs(fv[1], sv[1]);
            w0.z = packfs(fv[2], sv[2]); w0.w = packfs(fv[3], sv[3]);
            w1.x = packfs(fv[4], sv[4]); w1.y = packfs(fv[5], sv[5]);
            w1.z = packfs(fv[6], sv[6]); w1.w = packfs(fv[7], sv[7]);
            *(uint4*)&d_Bb[(size_t)n * 64 + tx * 8]     = w0;
            *(uint4*)&d_Bb[(size_t)n * 64 + tx * 8 + 4] = w1;
        }
    }
}

// ---------------- edge pass: warp per dst node, bf16 gathers ----------------
__global__ __launch_bounds__(256) void edge_agg_kernel(const float* __restrict__ Wf,
                                                       const float* __restrict__ bf,
                                                       const float* __restrict__ Ws,
                                                       const float* __restrict__ bs) {
    __shared__ float ssum[64], ssq[64];
    int tid = threadIdx.x;
    if (tid < 64) { ssum[tid] = 0.f; ssq[tid] = 0.f; }
    __syncthreads();

    int lane = tid & 31, w = tid >> 5;
    int node = blockIdx.x * 8 + w;
    if (node < NN) {
        int c0 = lane, c1 = lane + 32;
        const float* Ap = d_A + (size_t)node * 128;
        float af0 = Ap[c0], af1 = Ap[c1], as0 = Ap[64 + c0], as1 = Ap[64 + c1];
        float wf0 = Wf[128 * 64 + c0], wf1 = Wf[128 * 64 + c1];
        float ws0 = Ws[128 * 64 + c0], ws1 = Ws[128 * 64 + c1];
        float vbf0 = bf[c0], vbf1 = bf[c1], vbs0 = bs[c0], vbs1 = bs[c1];
        float acc0 = 0.f, acc1 = 0.f;
        int e0 = d_off[node], e1 = d_off[node + 1];

        #define EDGE_BODY(p)                                                       \
        {                                                                          \
            const unsigned int* Bp = d_Bb + (size_t)(p).x * 64;                    \
            float ea = __int_as_float((p).y);                                      \
            unsigned int w0 = Bp[c0];                                              \
            unsigned int w1 = Bp[c1];                                              \
            float bf0 = __int_as_float(w0 & 0xffff0000u);                          \
            float bs0v = __int_as_float(w0 << 16);                                 \
            float bf1 = __int_as_float(w1 & 0xffff0000u);                          \
            float bs1v = __int_as_float(w1 << 16);                                 \
            float tf0 = af0 + bf0 + fmaf(ea, wf0, vbf0);                           \
            float ts0 = as0 + bs0v + fmaf(ea, ws0, vbs0);                          \
            float tf1 = af1 + bf1 + fmaf(ea, wf1, vbf1);                           \
            float ts1 = as1 + bs1v + fmaf(ea, ws1, vbs1);                          \
            float sg0 = sigmoid_t(tf0);                                            \
            float sg1 = sigmoid_t(tf1);                                            \
            float sp0 = softplus_f(ts0);                                           \
            float sp1 = softplus_f(ts1);                                           \
            acc0 = fmaf(sg0, sp0, acc0);                                           \
            acc1 = fmaf(sg1, sp1, acc1);                                           \
        }

        int e = e0;
        for (; e + 3 < e1; e += 4) {
            int2 p0 = d_edge[e];
            int2 p1 = d_edge[e + 1];
            int2 p2 = d_edge[e + 2];
            int2 p3 = d_edge[e + 3];
            EDGE_BODY(p0) EDGE_BODY(p1) EDGE_BODY(p2) EDGE_BODY(p3)
        }
        for (; e < e1; e++) {
            int2 p0 = d_edge[e];
            EDGE_BODY(p0)
        }
        #undef EDGE_BODY

        d_y[(size_t)node * 64 + c0] = acc0;
        d_y[(size_t)node * 64 + c1] = acc1;
        atomicAdd(&ssum[c0], acc0); atomicAdd(&ssq[c0], acc0 * acc0);
        atomicAdd(&ssum[c1], acc1); atomicAdd(&ssq[c1], acc1 * acc1);
    }
    __syncthreads();
    if (tid < 64) {
        atomicAdd(&d_stats[tid], (double)ssum[tid]);
        atomicAdd(&d_stats[64 + tid], (double)ssq[tid]);
    }
}

// ---------------- final MLP ----------------
__global__ void mlp_kernel(const float* __restrict__ W1, const float* __restrict__ b1,
                           const float* __restrict__ W2, const float* __restrict__ b2,
                           float* __restrict__ out) {
    __shared__ float p[64];
    __shared__ float h1[32];
    int g = blockIdx.x;
    int tid = threadIdx.x;
    float inv = 1.f / fmaxf((float)d_gcnt[g], 1.f);
    p[tid] = d_pool[g * 64 + tid] * inv;
    __syncthreads();
    if (tid < 32) {
        float a = b1[tid];
        #pragma unroll
        for (int k = 0; k < 64; k++) a = fmaf(p[k], W1[k * 32 + tid], a);
        h1[tid] = fmaxf(a, 0.f);
    }
    __syncthreads();
    if (tid < 32) {
        float v = h1[tid] * W2[tid];
        #pragma unroll
        for (int o = 16; o > 0; o >>= 1) v += __shfl_down_sync(0xffffffffu, v, o);
        if (tid == 0) out[g] = v + b2[0];
    }
}

// ---------------- launcher ----------------
extern "C" void kernel_launch(void* const* d_in, const int* in_sizes, int n_in,
                              void* d_out, int out_size) {
    const float* x     = (const float*)d_in[0];
    const int*   ei    = (const int*)d_in[1];
    const float* ea    = (const float*)d_in[2];
    const int*   batch = (const int*)d_in[3];
    const float* W_in  = (const float*)d_in[4];
    const float* b_in  = (const float*)d_in[5];
    const float* g0    = (const float*)d_in[6];
    const float* beta0 = (const float*)d_in[7];
    const float* Wf[3] = {(const float*)d_in[8],  (const float*)d_in[14], (const float*)d_in[20]};
    const float* bf[3] = {(const float*)d_in[9],  (const float*)d_in[15], (const float*)d_in[21]};
    const float* Ws[3] = {(const float*)d_in[10], (const float*)d_in[16], (const float*)d_in[22]};
    const float* bs[3] = {(const float*)d_in[11], (const float*)d_in[17], (const float*)d_in[23]};
    const float* gg[3] = {(const float*)d_in[12], (const float*)d_in[18], (const float*)d_in[24]};
    const float* bb[3] = {(const float*)d_in[13], (const float*)d_in[19], (const float*)d_in[25]};
    const float* W1 = (const float*)d_in[26];
    const float* b1 = (const float*)d_in[27];
    const float* W2 = (const float*)d_in[28];
    const float* b2 = (const float*)d_in[29];
    float* out = (float*)d_out;

    init_kernel<<<(NN + 255) / 256, 256>>>();
    hist_kernel<<<(NE + 255) / 256, 256>>>(ei, batch);
    scan_kernel<<<1, 1024>>>();
    scatter_kernel<<<(NE + 255) / 256, 256>>>(ei, ea);

    input_kernel<<<(NN + 63) / 64, 256>>>(x, W_in, b_in);
    bn_prep_kernel<<<1, 64>>>(g0, beta0);
    bn_apply_kernel<<<(NN * NC + 255) / 256, 256>>>(0, 1);

    for (int l = 0; l < 3; l++) {
        gemm_AB_kernel<<<dim3((NN + 127) / 128, 2), 256>>>(Wf[l], Ws[l]);
        edge_agg_kernel<<<(NN + 7) / 8, 256>>>(Wf[l], bf[l], Ws[l], bs[l]);
        bn_prep_kernel<<<1, 64>>>(gg[l], bb[l]);
        if (l < 2)
            bn_apply_kernel<<<(NN * NC + 255) / 256, 256>>>(1, 1);
        else
            bn_pool_kernel<<<(NN * NC + 1023) / 1024, 1024>>>(batch);
    }

    mlp_kernel<<<NG, 64>>>(W1, b1, W2, b2, out);
}

// round 8
// speedup vs baseline: 1.9018x; 1.3225x over previous
#include <cuda_runtime.h>
#include <cuda_bf16.h>
#include <math.h>

#define NN 100000
#define NE 1200000
#define NC 64
#define NG 256
#define EPSBN 1e-5f
#define LOG2E 1.44269504f
#define HALF_LN2 0.34657359f

#define EWARPS 8192
#define ECHUNK ((NE + EWARPS - 1) / EWARPS)

// ---------------- static scratch ----------------
__device__ float        d_h[NN * NC];
__device__ float        d_y[NN * NC];
__device__ float        d_A[NN * 2 * NC];   // [f+bf (64) | log2e*(s+bs) (64)] per node
__device__ unsigned int d_Bb[NN * NC];      // bf16x2: hi = f, lo = log2e*s
__device__ int          d_cnt[NN];
__device__ int          d_fill[NN];
__device__ int          d_off[NN + 1];
__device__ int2         d_edge[NE];         // (src, ea bits) sorted by dst
__device__ int          d_dst[NE];          // dst sorted (ascending)
__device__ double       d_stats[2 * NC];
__device__ float        d_bnscale[NC];
__device__ float        d_bnshift[NC];
__device__ float        d_pool[NG * NC];
__device__ int          d_gcnt[NG];

// ---------------- helpers ----------------
__device__ __forceinline__ unsigned long long pack2(float x, float y) {
    unsigned long long r;
    asm("mov.b64 %0, {%1, %2};" : "=l"(r) : "f"(x), "f"(y));
    return r;
}
__device__ __forceinline__ void unpack2(unsigned long long v, float& x, float& y) {
    asm("mov.b64 {%0, %1}, %2;" : "=f"(x), "=f"(y) : "l"(v));
}
__device__ __forceinline__ unsigned long long ffma2(unsigned long long a,
                                                    unsigned long long b,
                                                    unsigned long long c) {
    unsigned long long d;
    asm("fma.rn.f32x2 %0, %1, %2, %3;" : "=l"(d) : "l"(a), "l"(b), "l"(c));
    return d;
}
__device__ __forceinline__ float tanh_f(float x) {
    float t;
    asm("tanh.approx.f32 %0, %1;" : "=f"(t) : "f"(x));
    return t;
}
__device__ __forceinline__ float ex2_f(float x) {
    float t;
    asm("ex2.approx.ftz.f32 %0, %1;" : "=f"(t) : "f"(x));
    return t;
}
__device__ __forceinline__ float lg2_f(float x) {
    float t;
    asm("lg2.approx.f32 %0, %1;" : "=f"(t) : "f"(x));
    return t;
}
// pack (f -> high 16, s -> low 16)
__device__ __forceinline__ unsigned int packfs(float f, float s) {
    __nv_bfloat162 h2 = __floats2bfloat162_rn(s, f);
    return *reinterpret_cast<unsigned int*>(&h2);
}

// ---------------- init ----------------
__global__ void init_kernel() {
    int i = blockIdx.x * blockDim.x + threadIdx.x;
    if (i < NN) { d_cnt[i] = 0; d_fill[i] = 0; }
    if (i < NG * NC) d_pool[i] = 0.f;
    if (i < NG) d_gcnt[i] = 0;
    if (i < 2 * NC) d_stats[i] = 0.0;
}

__global__ void hist_kernel(const int* __restrict__ ei, const int* __restrict__ batch) {
    int e = blockIdx.x * blockDim.x + threadIdx.x;
    if (e < NE) atomicAdd(&d_cnt[ei[NE + e]], 1);
    if (e < NN) atomicAdd(&d_gcnt[batch[e]], 1);
}

__global__ void scan_kernel() {
    const int CH = (NN + 1023) / 1024;
    int tid = threadIdx.x;
    int start = tid * CH;
    int end = min(start + CH, NN);
    int s = 0;
    for (int i = start; i < end; i++) s += d_cnt[i];

    __shared__ int warp_sums[32];
    int lane = tid & 31, w = tid >> 5;
    int incl = s;
    #pragma unroll
    for (int o = 1; o < 32; o <<= 1) {
        int t = __shfl_up_sync(0xffffffffu, incl, o);
        if (lane >= o) incl += t;
    }
    if (lane == 31) warp_sums[w] = incl;
    __syncthreads();
    if (w == 0) {
        int v = warp_sums[lane];
        #pragma unroll
        for (int o = 1; o < 32; o <<= 1) {
            int t = __shfl_up_sync(0xffffffffu, v, o);
            if (lane >= o) v += t;
        }
        warp_sums[lane] = v;
    }
    __syncthreads();
    int excl = incl - s + (w > 0 ? warp_sums[w - 1] : 0);
    int run = excl;
    for (int i = start; i < end; i++) { d_off[i] = run; run += d_cnt[i]; }
    if (tid == 1023) d_off[NN] = NE;
}

__global__ void scatter_kernel(const int* __restrict__ ei, const float* __restrict__ ea) {
    int e = blockIdx.x * blockDim.x + threadIdx.x;
    if (e < NE) {
        int d = ei[NE + e];
        int p = atomicAdd(&d_fill[d], 1);
        int idx = d_off[d] + p;
        d_edge[idx] = make_int2(ei[e], __float_as_int(ea[e]));
        d_dst[idx] = d;
    }
}

// ---------------- BN prep (reads stats, zeroes them) ----------------
__global__ void bn_prep_kernel(const float* __restrict__ g, const float* __restrict__ beta) {
    int c = threadIdx.x;
    if (c < NC) {
        double mu = d_stats[c] * (1.0 / (double)NN);
        double var = d_stats[NC + c] * (1.0 / (double)NN) - mu * mu;
        float rs = rsqrtf((float)var + EPSBN);
        float sc = g[c] * rs;
        d_bnscale[c] = sc;
        d_bnshift[c] = beta[c] - (float)mu * sc;
        d_stats[c] = 0.0;
        d_stats[NC + c] = 0.0;
    }
}

// ---------------- stats over d_y ----------------
__global__ __launch_bounds__(256) void stats_kernel() {
    __shared__ float ssum[64], ssq[64];
    int tid = threadIdx.x;
    if (tid < 64) { ssum[tid] = 0.f; ssq[tid] = 0.f; }
    __syncthreads();
    int c = tid & 63;
    float ls = 0.f, lq = 0.f;
    const size_t stride = (size_t)256 * 1024;   // multiple of 64 -> c constant
    for (size_t idx = (size_t)blockIdx.x * 256 + tid; idx < (size_t)NN * NC; idx += stride) {
        float v = d_y[idx];
        ls += v;
        lq = fmaf(v, v, lq);
    }
    atomicAdd(&ssum[c], ls);
    atomicAdd(&ssq[c], lq);
    __syncthreads();
    if (tid < 64) {
        atomicAdd(&d_stats[tid], (double)ssum[tid]);
        atomicAdd(&d_stats[64 + tid], (double)ssq[tid]);
    }
}

// ---------------- input layer ----------------
__global__ __launch_bounds__(256) void input_kernel(const float* __restrict__ x,
                                                    const float* __restrict__ W,
                                                    const float* __restrict__ b) {
    __shared__ float ws[12 * 64];
    __shared__ float xs[64 * 12];
    __shared__ float ssum[64], ssq[64];
    int tid = threadIdx.x;
    int base = blockIdx.x * 64;
    for (int i = tid; i < 12 * 64; i += 256) ws[i] = W[i];
    for (int i = tid; i < 64 * 12; i += 256) {
        int n = i / 12;
        xs[i] = (base + n < NN) ? x[(size_t)(base + n) * 12 + (i % 12)] : 0.f;
    }
    if (tid < 64) { ssum[tid] = 0.f; ssq[tid] = 0.f; }
    __syncthreads();
    int c = tid & 63;
    float bc = b[c];
    float lsum = 0.f, lsq = 0.f;
    #pragma unroll
    for (int p = 0; p < 16; p++) {
        int n = p * 4 + (tid >> 6);
        float acc = bc;
        #pragma unroll
        for (int k = 0; k < 12; k++) acc = fmaf(xs[n * 12 + k], ws[k * 64 + c], acc);
        if (base + n < NN) {
            d_y[(size_t)(base + n) * 64 + c] = acc;
            lsum += acc;
            lsq = fmaf(acc, acc, lsq);
        }
    }
    atomicAdd(&ssum[c], lsum);
    atomicAdd(&ssq[c], lsq);
    __syncthreads();
    if (tid < 64) {
        atomicAdd(&d_stats[tid], (double)ssum[tid]);
        atomicAdd(&d_stats[64 + tid], (double)ssq[tid]);
    }
}

// ---------------- unified GEMM: BN(prev)+res+relu fused, all 4 quadrants ----------------
// smem: hsT [64][65] floats, then wsm2 u64[64][128]
extern __shared__ float smem_g[];
__global__ __launch_bounds__(256) void gemm_kernel(const float* __restrict__ Wf,
                                                   const float* __restrict__ Ws,
                                                   const float* __restrict__ bfv,
                                                   const float* __restrict__ bsv,
                                                   int residual) {
    float* hsT = smem_g;                                         // [64][65]
    unsigned long long* wsm2 = (unsigned long long*)(smem_g + 64 * 65);  // [64][128]
    __shared__ float sbn[128];
    int tid = threadIdx.x;
    int nb = blockIdx.x * 64;

    if (tid < 64) { sbn[tid] = d_bnscale[tid]; sbn[64 + tid] = d_bnshift[tid]; }
    __syncthreads();

    // weights: wsm2[k*128 + ch] = (Wf[row][c], Ws[row][c]); row = (ch>=64?64:0)+k, c=ch&63
    #pragma unroll
    for (int m = 0; m < 32; m++) {
        int lin = m * 256 + tid;
        int k = lin >> 7, ch = lin & 127;
        int row = ((ch >> 6) << 6) + k;
        int c = ch & 63;
        wsm2[lin] = pack2(Wf[row * 64 + c], Ws[row * 64 + c]);
    }
    // h = relu(bn(y) [+ h_prev]); write d_h; zero d_y
    #pragma unroll
    for (int m = 0; m < 16; m++) {
        int lin = m * 256 + tid;
        int a = lin >> 6, c = lin & 63;
        int n = nb + a;
        float v = 0.f;
        if (n < NN) {
            size_t g = (size_t)n * 64 + c;
            v = fmaf(d_y[g], sbn[c], sbn[64 + c]);
            if (residual) v += d_h[g];
            v = fmaxf(v, 0.f);
            d_h[g] = v;
            d_y[g] = 0.f;
        }
        hsT[c * 65 + a] = v;
    }
    __syncthreads();

    int ty = tid >> 5, tx = tid & 31;
    int chbase = ((tx & 15) << 2) + ((tx >> 4) << 6);
    unsigned long long acc[8][4];
    #pragma unroll
    for (int j = 0; j < 8; j++)
        #pragma unroll
        for (int q = 0; q < 4; q++) acc[j][q] = 0ull;

    #pragma unroll 4
    for (int k = 0; k < 64; k++) {
        const unsigned long long* wr = &wsm2[k * 128 + chbase];
        ulonglong2 bq0 = *(const ulonglong2*)(wr);
        ulonglong2 bq1 = *(const ulonglong2*)(wr + 2);
        const float* hr = &hsT[k * 65 + ty * 8];
        #pragma unroll
        for (int j = 0; j < 8; j++) {
            float a = hr[j];
            unsigned long long aa = pack2(a, a);
            acc[j][0] = ffma2(aa, bq0.x, acc[j][0]);
            acc[j][1] = ffma2(aa, bq0.y, acc[j][1]);
            acc[j][2] = ffma2(aa, bq1.x, acc[j][2]);
            acc[j][3] = ffma2(aa, bq1.y, acc[j][3]);
        }
    }

    bool aSide = (tx < 16);
    int ch0 = (tx & 15) * 4;
    float bfr[4], bsr[4];
    if (aSide) {
        #pragma unroll
        for (int q = 0; q < 4; q++) {
            bfr[q] = bfv[ch0 + q];
            bsr[q] = LOG2E * bsv[ch0 + q];
        }
    }
    #pragma unroll
    for (int j = 0; j < 8; j++) {
        int n = nb + ty * 8 + j;
        if (n >= NN) continue;
        #pragma unroll
        for (int q = 0; q < 4; q++) {
            float f, s;
            unpack2(acc[j][q], f, s);
            if (aSide) {
                d_A[(size_t)n * 128 + ch0 + q] = f + bfr[q];
                d_A[(size_t)n * 128 + 64 + ch0 + q] = fmaf(LOG2E, s, bsr[q]);
            } else {
                d_Bb[(size_t)n * 64 + ch0 + q] = packfs(f, LOG2E * s);
            }
        }
    }
}

// ---------------- edge pass: warp-chunk scan, register accum, atomic flush ----------------
__global__ __launch_bounds__(256) void edge_kernel(const float* __restrict__ Wf,
                                                   const float* __restrict__ Ws) {
    int lane = threadIdx.x & 31;
    int gw = blockIdx.x * 8 + (threadIdx.x >> 5);
    int e = gw * ECHUNK;
    int e1 = min(e + ECHUNK, NE);
    if (e >= e1) return;
    int c0 = lane, c1 = lane + 32;
    float wf0 = Wf[128 * 64 + c0], wf1 = Wf[128 * 64 + c1];
    float ws0 = LOG2E * Ws[128 * 64 + c0], ws1 = LOG2E * Ws[128 * 64 + c1];

    int cur = d_dst[e];
    int2 m = d_edge[e];
    {
        const unsigned int* Bp = d_Bb + (size_t)m.x * 64;
        unsigned int w0 = Bp[c0], w1 = Bp[c1];
        const float* Ap = d_A + (size_t)cur * 128;
        float afb0 = Ap[c0], afb1 = Ap[c1], asb0 = Ap[64 + c0], asb1 = Ap[64 + c1];
        float aT0 = 0.f, aL0 = 0.f, aT1 = 0.f, aL1 = 0.f;

        while (true) {
            bool has_n = (e + 1 < e1);
            int dst_n = 0;
            int2 m_n;
            unsigned int w0_n = 0, w1_n = 0;
            if (has_n) {
                dst_n = d_dst[e + 1];
                m_n = d_edge[e + 1];
                const unsigned int* Bn = d_Bb + (size_t)m_n.x * 64;
                w0_n = Bn[c0];
                w1_n = Bn[c1];
            }
            // process current edge (its dst == cur by construction)
            float ea = __int_as_float(m.y);
            float bf0 = __int_as_float(w0 & 0xffff0000u);
            float bs0 = __int_as_float(w0 << 16);
            float bf1 = __int_as_float(w1 & 0xffff0000u);
            float bs1 = __int_as_float(w1 << 16);
            float tf0 = fmaf(ea, wf0, afb0) + bf0;
            float ts0 = fmaf(ea, ws0, asb0) + bs0;
            float tf1 = fmaf(ea, wf1, afb1) + bf1;
            float ts1 = fmaf(ea, ws1, asb1) + bs1;
            float t0 = tanh_f(0.5f * tf0);
            float t1 = tanh_f(0.5f * tf1);
            float l0 = lg2_f(1.f + ex2_f(ts0));
            float l1 = lg2_f(1.f + ex2_f(ts1));
            aT0 = fmaf(t0, l0, aT0); aL0 += l0;
            aT1 = fmaf(t1, l1, aT1); aL1 += l1;

            if (!has_n) break;
            if (dst_n != cur) {
                atomicAdd(&d_y[(size_t)cur * 64 + c0], HALF_LN2 * (aT0 + aL0));
                atomicAdd(&d_y[(size_t)cur * 64 + c1], HALF_LN2 * (aT1 + aL1));
                cur = dst_n;
                const float* An = d_A + (size_t)cur * 128;
                afb0 = An[c0]; afb1 = An[c1]; asb0 = An[64 + c0]; asb1 = An[64 + c1];
                aT0 = 0.f; aL0 = 0.f; aT1 = 0.f; aL1 = 0.f;
            }
            m = m_n; w0 = w0_n; w1 = w1_n; e++;
        }
        atomicAdd(&d_y[(size_t)cur * 64 + c0], HALF_LN2 * (aT0 + aL0));
        atomicAdd(&d_y[(size_t)cur * 64 + c1], HALF_LN2 * (aT1 + aL1));
    }
}

// ---------------- BN apply + pooled (last layer, batch sorted) ----------------
__global__ __launch_bounds__(1024) void bn_pool_kernel(const int* __restrict__ batch) {
    __shared__ float psum[64];
    __shared__ int sg[2];
    int tid = threadIdx.x;
    int idx = blockIdx.x * 1024 + tid;
    int node = idx >> 6;
    int c = idx & 63;
    float v = fmaf(d_y[idx], d_bnscale[c], d_bnshift[c]) + d_h[idx];
    d_h[idx] = v;
    int g = batch[node];
    if (tid == 0)    sg[0] = g;
    if (tid == 1023) sg[1] = g;
    __syncthreads();
    int g0 = sg[0], g1 = sg[1];
    for (int gg = g0; gg <= g1; gg++) {
        if (tid < 64) psum[tid] = 0.f;
        __syncthreads();
        if (g == gg) atomicAdd(&psum[c], v);
        __syncthreads();
        if (tid < 64 && psum[tid] != 0.f) atomicAdd(&d_pool[gg * 64 + tid], psum[tid]);
        __syncthreads();
    }
}

// ---------------- final MLP ----------------
__global__ void mlp_kernel(const float* __restrict__ W1, const float* __restrict__ b1,
                           const float* __restrict__ W2, const float* __restrict__ b2,
                           float* __restrict__ out) {
    __shared__ float p[64];
    __shared__ float h1[32];
    int g = blockIdx.x;
    int tid = threadIdx.x;
    float inv = 1.f / fmaxf((float)d_gcnt[g], 1.f);
    p[tid] = d_pool[g * 64 + tid] * inv;
    __syncthreads();
    if (tid < 32) {
        float a = b1[tid];
        #pragma unroll
        for (int k = 0; k < 64; k++) a = fmaf(p[k], W1[k * 32 + tid], a);
        h1[tid] = fmaxf(a, 0.f);
    }
    __syncthreads();
    if (tid < 32) {
        float v = h1[tid] * W2[tid];
        #pragma unroll
        for (int o = 16; o > 0; o >>= 1) v += __shfl_down_sync(0xffffffffu, v, o);
        if (tid == 0) out[g] = v + b2[0];
    }
}

// ---------------- launcher ----------------
extern "C" void kernel_launch(void* const* d_in, const int* in_sizes, int n_in,
                              void* d_out, int out_size) {
    const float* x     = (const float*)d_in[0];
    const int*   ei    = (const int*)d_in[1];
    const float* ea    = (const float*)d_in[2];
    const int*   batch = (const int*)d_in[3];
    const float* W_in  = (const float*)d_in[4];
    const float* b_in  = (const float*)d_in[5];
    const float* g0    = (const float*)d_in[6];
    const float* beta0 = (const float*)d_in[7];
    const float* Wf[3] = {(const float*)d_in[8],  (const float*)d_in[14], (const float*)d_in[20]};
    const float* bf[3] = {(const float*)d_in[9],  (const float*)d_in[15], (const float*)d_in[21]};
    const float* Ws[3] = {(const float*)d_in[10], (const float*)d_in[16], (const float*)d_in[22]};
    const float* bs[3] = {(const float*)d_in[11], (const float*)d_in[17], (const float*)d_in[23]};
    const float* gg[3] = {(const float*)d_in[12], (const float*)d_in[18], (const float*)d_in[24]};
    const float* bb[3] = {(const float*)d_in[13], (const float*)d_in[19], (const float*)d_in[25]};
    const float* W1 = (const float*)d_in[26];
    const float* b1 = (const float*)d_in[27];
    const float* W2 = (const float*)d_in[28];
    const float* b2 = (const float*)d_in[29];
    float* out = (float*)d_out;

    const int GEMM_SMEM = 64 * 65 * 4 + 64 * 128 * 8;   // 82176 bytes
    cudaFuncSetAttribute(gemm_kernel, cudaFuncAttributeMaxDynamicSharedMemorySize, GEMM_SMEM);

    init_kernel<<<(NN + 255) / 256, 256>>>();
    hist_kernel<<<(NE + 255) / 256, 256>>>(ei, batch);
    scan_kernel<<<1, 1024>>>();
    scatter_kernel<<<(NE + 255) / 256, 256>>>(ei, ea);

    input_kernel<<<(NN + 63) / 64, 256>>>(x, W_in, b_in);
    bn_prep_kernel<<<1, 64>>>(g0, beta0);

    for (int l = 0; l < 3; l++) {
        gemm_kernel<<<(NN + 63) / 64, 256, GEMM_SMEM>>>(Wf[l], Ws[l], bf[l], bs[l],
                                                        (l == 0) ? 0 : 1);
        edge_kernel<<<EWARPS / 8, 256>>>(Wf[l], Ws[l]);
        stats_kernel<<<1024, 256>>>();
        bn_prep_kernel<<<1, 64>>>(gg[l], bb[l]);
    }

    bn_pool_kernel<<<(NN * NC + 1023) / 1024, 1024>>>(batch);
    mlp_kernel<<<NG, 64>>>(W1, b1, W2, b2, out);
}